// round 3
// baseline (speedup 1.0000x reference)
#include <cuda_runtime.h>
#include <cuda_bf16.h>
#include <cstdint>

#define N_NODES 50000
#define N_EDGES 800000
#define DIM 128
#define N_LAYERS 5

// ---------------------------------------------------------------------------
// Scratch (allocation-free rule: __device__ globals, referenced directly)
// ---------------------------------------------------------------------------
__device__ float g_h[N_NODES * DIM];       // 25.6 MB: post-GEMM features
__device__ float g_acc[N_NODES * DIM];     // 25.6 MB: layer output (intermediate)
__device__ int   g_count[N_NODES];         // in-degree counts (no self loop)
__device__ int   g_fill[N_NODES];          // CSR fill cursors
__device__ int   g_rowptr[N_NODES + 1];    // CSR row pointers
__device__ float g_dinv[N_NODES];          // rsqrt(deg incl. self loop)
__device__ int2  g_adj[N_EDGES];           // CSR: (src, bitcast(dinv[src]))
__device__ int   g_is64;                   // edge_index dtype flag

// ---------------------------------------------------------------------------
// Edge accessor: robust to int64-vs-int32 edge_index storage
// ---------------------------------------------------------------------------
__device__ __forceinline__ int load_edge(const void* e, long long idx, int is64) {
    if (is64) return (int)((const long long*)e)[idx];
    return ((const int*)e)[idx];
}

__global__ void detect_dtype_kernel(const void* e) {
    if (blockIdx.x == 0 && threadIdx.x == 0) {
        const unsigned* w = (const unsigned*)e;
        int is64 = 1;
        for (int i = 0; i < 128; i++) {
            if (w[2 * i + 1] != 0u) { is64 = 0; break; }
        }
        g_is64 = is64;
    }
}

__global__ void zero_counts_kernel() {
    int i = blockIdx.x * blockDim.x + threadIdx.x;
    if (i < N_NODES) { g_count[i] = 0; g_fill[i] = 0; }
}

__global__ void hist_kernel(const void* e) {
    int i = blockIdx.x * blockDim.x + threadIdx.x;
    if (i < N_EDGES) {
        int d = load_edge(e, (long long)N_EDGES + i, g_is64);
        atomicAdd(&g_count[d], 1);
    }
}

__global__ void dinv_kernel() {
    int i = blockIdx.x * blockDim.x + threadIdx.x;
    if (i < N_NODES) g_dinv[i] = rsqrtf((float)(g_count[i] + 1));
}

// Single-block exclusive scan of g_count -> g_rowptr (50k elems, 1024 threads)
__global__ void scan_kernel() {
    __shared__ int s[1024];
    int tid = threadIdx.x;
    int carry = 0;
    for (int base = 0; base < N_NODES; base += 1024) {
        int i = base + tid;
        int v = (i < N_NODES) ? g_count[i] : 0;
        s[tid] = v;
        __syncthreads();
        // Hillis-Steele inclusive scan
        for (int off = 1; off < 1024; off <<= 1) {
            int t = (tid >= off) ? s[tid - off] : 0;
            __syncthreads();
            s[tid] += t;
            __syncthreads();
        }
        if (i < N_NODES) g_rowptr[i] = carry + s[tid] - v;  // exclusive
        carry += s[1023];
        __syncthreads();
    }
    if (tid == 0) g_rowptr[N_NODES] = carry;  // == N_EDGES
}

__global__ void build_csr_kernel(const void* e) {
    int i = blockIdx.x * blockDim.x + threadIdx.x;
    if (i < N_EDGES) {
        int is64 = g_is64;
        int s = load_edge(e, i, is64);
        int d = load_edge(e, (long long)N_EDGES + i, is64);
        int pos = g_rowptr[d] + atomicAdd(&g_fill[d], 1);
        g_adj[pos] = make_int2(s, __float_as_int(g_dinv[s]));
    }
}

// ---------------------------------------------------------------------------
// SGEMM: C[M,128] = A[M,128] @ W[128,128]
// BM=128, BN=128, BK=32, 256 threads, 8x8 microtile per thread
// ---------------------------------------------------------------------------
#define BM 128
#define BN 128
#define BK 32
#define TM 8
#define TN 8

__global__ __launch_bounds__(256) void gemm_kernel(
    const float* __restrict__ A, const float* __restrict__ W,
    float* __restrict__ C, int M)
{
    __shared__ float As[BK][BM + 4];
    __shared__ float Ws[BK][BN];

    int tid = threadIdx.x;
    int rowBase = blockIdx.x * BM;
    int tx = tid % 16;
    int ty = tid / 16;

    float acc[TM][TN];
#pragma unroll
    for (int i = 0; i < TM; i++)
#pragma unroll
        for (int j = 0; j < TN; j++) acc[i][j] = 0.0f;

    for (int k0 = 0; k0 < DIM; k0 += BK) {
#pragma unroll
        for (int i = 0; i < 4; i++) {
            int idx = tid + i * 256;
            int r = idx / (BK / 4);
            int c4 = idx % (BK / 4);
            float4 v = make_float4(0.f, 0.f, 0.f, 0.f);
            int grow = rowBase + r;
            if (grow < M) v = *(const float4*)&A[(size_t)grow * DIM + k0 + c4 * 4];
            As[c4 * 4 + 0][r] = v.x;
            As[c4 * 4 + 1][r] = v.y;
            As[c4 * 4 + 2][r] = v.z;
            As[c4 * 4 + 3][r] = v.w;
        }
#pragma unroll
        for (int i = 0; i < 4; i++) {
            int idx = tid + i * 256;
            int r = idx / (BN / 4);
            int c4 = idx % (BN / 4);
            *(float4*)&Ws[r][c4 * 4] = *(const float4*)&W[(size_t)(k0 + r) * DIM + c4 * 4];
        }
        __syncthreads();

#pragma unroll
        for (int k = 0; k < BK; k++) {
            float4 a0 = *(const float4*)&As[k][ty * TM];
            float4 a1 = *(const float4*)&As[k][ty * TM + 4];
            float4 b0 = *(const float4*)&Ws[k][tx * TN];
            float4 b1 = *(const float4*)&Ws[k][tx * TN + 4];
            float a[TM] = {a0.x, a0.y, a0.z, a0.w, a1.x, a1.y, a1.z, a1.w};
            float b[TN] = {b0.x, b0.y, b0.z, b0.w, b1.x, b1.y, b1.z, b1.w};
#pragma unroll
            for (int i = 0; i < TM; i++)
#pragma unroll
                for (int j = 0; j < TN; j++) acc[i][j] += a[i] * b[j];
        }
        __syncthreads();
    }

#pragma unroll
    for (int i = 0; i < TM; i++) {
        int grow = rowBase + ty * TM + i;
        if (grow < M) {
            *(float4*)&C[(size_t)grow * DIM + tx * TN] =
                make_float4(acc[i][0], acc[i][1], acc[i][2], acc[i][3]);
            *(float4*)&C[(size_t)grow * DIM + tx * TN + 4] =
                make_float4(acc[i][4], acc[i][5], acc[i][6], acc[i][7]);
        }
    }
}

// ---------------------------------------------------------------------------
// Fused CSR gather + self loop + scale + bias + ReLU
// One warp per node. Lane owns a float4 column slice (lane*4 .. lane*4+3).
// out[d] = relu( dinv[d] * ( sum_j dinv[s_j]*h[s_j] + dinv[d]*h[d] ) + bias )
// ---------------------------------------------------------------------------
__global__ __launch_bounds__(256) void gather_kernel(
    const float* __restrict__ h, const float* __restrict__ bias,
    float* __restrict__ out)
{
    int warp = (blockIdx.x * blockDim.x + threadIdx.x) >> 5;
    if (warp >= N_NODES) return;
    int lane = threadIdx.x & 31;
    int node = warp;
    int c = lane * 4;

    int start = g_rowptr[node];
    int end   = g_rowptr[node + 1];
    float dd  = g_dinv[node];

    // self-loop term (pre outer scale): dinv[d] * h[d]
    float4 hv = *(const float4*)&h[(size_t)node * DIM + c];
    float4 acc = make_float4(dd * hv.x, dd * hv.y, dd * hv.z, dd * hv.w);

    for (int j = start; j < end; j += 32) {
        int idx = j + lane;
        int2 ew = make_int2(0, 0);
        if (idx < end) ew = g_adj[idx];
        int cnt = min(32, end - j);
#pragma unroll 4
        for (int k = 0; k < cnt; k++) {
            int   s = __shfl_sync(0xFFFFFFFFu, ew.x, k);
            float w = __int_as_float(__shfl_sync(0xFFFFFFFFu, ew.y, k));
            float4 v = *(const float4*)&h[(size_t)s * DIM + c];
            acc.x += w * v.x;
            acc.y += w * v.y;
            acc.z += w * v.z;
            acc.w += w * v.w;
        }
    }

    float4 b = *(const float4*)&bias[c];
    acc.x = fmaxf(dd * acc.x + b.x, 0.0f);
    acc.y = fmaxf(dd * acc.y + b.y, 0.0f);
    acc.z = fmaxf(dd * acc.z + b.z, 0.0f);
    acc.w = fmaxf(dd * acc.w + b.w, 0.0f);
    *(float4*)&out[(size_t)node * DIM + c] = acc;
}

// ---------------------------------------------------------------------------
// Launch
// ---------------------------------------------------------------------------
extern "C" void kernel_launch(void* const* d_in, const int* in_sizes, int n_in,
                              void* d_out, int out_size)
{
    const float* x       = (const float*)d_in[0];
    const void*  eidx    = d_in[1];
    const float* weights = (const float*)d_in[2];
    const float* biases  = (const float*)d_in[3];
    float*       out     = (float*)d_out;

    float* h;   cudaGetSymbolAddress((void**)&h,   g_h);    // only used as kernel args
    float* acc; cudaGetSymbolAddress((void**)&acc, g_acc);

    // ---- Prologue: dtype detect, degrees, norm, CSR build ----
    detect_dtype_kernel<<<1, 32>>>(eidx);
    zero_counts_kernel<<<(N_NODES + 255) / 256, 256>>>();
    hist_kernel<<<(N_EDGES + 255) / 256, 256>>>(eidx);
    dinv_kernel<<<(N_NODES + 255) / 256, 256>>>();
    scan_kernel<<<1, 1024>>>();
    build_csr_kernel<<<(N_EDGES + 255) / 256, 256>>>(eidx);

    const int gemm_blocks   = (N_NODES + BM - 1) / BM;
    const int gather_blocks = (N_NODES * 32 + 255) / 256;

    const float* cur = x;
    for (int l = 0; l < N_LAYERS; l++) {
        const float* W = weights + (size_t)l * DIM * DIM;
        const float* b = biases + (size_t)l * DIM;
        float* layer_out = (l == N_LAYERS - 1) ? out : acc;

        gemm_kernel<<<gemm_blocks, 256>>>(cur, W, h, N_NODES);
        gather_kernel<<<gather_blocks, 256>>>(h, b, layer_out);

        cur = layer_out;
    }
}

// round 6
// speedup vs baseline: 1.1191x; 1.1191x over previous
#include <cuda_runtime.h>
#include <cuda_bf16.h>
#include <cstdint>

#define N_NODES 50000
#define N_EDGES 800000
#define DIM 128
#define N_LAYERS 5
#define SCAN_BLOCKS ((N_NODES + 255) / 256)   // 196

// ---------------------------------------------------------------------------
// Scratch (allocation-free rule: __device__ globals)
// ---------------------------------------------------------------------------
__device__ float g_h[N_NODES * DIM];       // post-GEMM features
__device__ float g_acc[N_NODES * DIM];     // layer output (intermediate)
__device__ int   g_count[N_NODES];
__device__ int   g_fill[N_NODES];
__device__ int   g_rowptr[N_NODES + 1];
__device__ float g_dinv[N_NODES];
__device__ int2  g_adj[N_EDGES];           // (src, bitcast(dinv[src]))
__device__ int   g_is64;
__device__ int   g_blocksum[SCAN_BLOCKS];
__device__ int   g_blockoff[SCAN_BLOCKS];

// ---------------------------------------------------------------------------
// Edge dtype handling (int64 vs int32 storage)
// ---------------------------------------------------------------------------
__device__ __forceinline__ int load_edge(const void* e, long long idx, int is64) {
    if (is64) return (int)((const long long*)e)[idx];
    return ((const int*)e)[idx];
}

__global__ void detect_dtype_kernel(const void* e) {
    if (threadIdx.x == 0) {
        const unsigned* w = (const unsigned*)e;
        int is64 = 1;
        for (int i = 0; i < 128; i++)
            if (w[2 * i + 1] != 0u) { is64 = 0; break; }
        g_is64 = is64;
    }
}

__global__ void zero_counts_kernel() {
    int i = blockIdx.x * blockDim.x + threadIdx.x;
    if (i < N_NODES) { g_count[i] = 0; g_fill[i] = 0; }
}

__global__ void hist_kernel(const void* e) {
    int i = blockIdx.x * blockDim.x + threadIdx.x;
    if (i < N_EDGES) {
        int d = load_edge(e, (long long)N_EDGES + i, g_is64);
        atomicAdd(&g_count[d], 1);
    }
}

__global__ void dinv_kernel() {
    int i = blockIdx.x * blockDim.x + threadIdx.x;
    if (i < N_NODES) g_dinv[i] = rsqrtf((float)(g_count[i] + 1));
}

// ---------------------------------------------------------------------------
// Two-level exclusive scan of g_count -> g_rowptr
// ---------------------------------------------------------------------------
__device__ __forceinline__ int warp_incl_scan(int x) {
#pragma unroll
    for (int o = 1; o < 32; o <<= 1) {
        int y = __shfl_up_sync(0xFFFFFFFFu, x, o);
        if ((threadIdx.x & 31) >= o) x += y;
    }
    return x;
}

__global__ void scan1_kernel() {
    __shared__ int wsum[8];
    int t = threadIdx.x, b = blockIdx.x;
    int i = b * 256 + t;
    int v = (i < N_NODES) ? g_count[i] : 0;
    int x = warp_incl_scan(v);
    if ((t & 31) == 31) wsum[t >> 5] = x;
    __syncthreads();
    if (t == 0) {
        int run = 0;
#pragma unroll
        for (int w = 0; w < 8; w++) { int tmp = wsum[w]; wsum[w] = run; run += tmp; }
        g_blocksum[b] = run;
    }
    __syncthreads();
    if (i < N_NODES) g_rowptr[i] = x - v + wsum[t >> 5];  // exclusive, pre-offset
}

__global__ void scan2_kernel() {
    __shared__ int wsum[8];
    int t = threadIdx.x;
    int v = (t < SCAN_BLOCKS) ? g_blocksum[t] : 0;
    int x = warp_incl_scan(v);
    if ((t & 31) == 31) wsum[t >> 5] = x;
    __syncthreads();
    if (t == 0) {
        int run = 0;
#pragma unroll
        for (int w = 0; w < 8; w++) { int tmp = wsum[w]; wsum[w] = run; run += tmp; }
    }
    __syncthreads();
    if (t < SCAN_BLOCKS) g_blockoff[t] = x - v + wsum[t >> 5];
}

__global__ void scan3_kernel() {
    int i = blockIdx.x * blockDim.x + threadIdx.x;
    if (i < N_NODES) g_rowptr[i] += g_blockoff[i >> 8];
    if (i == 0) g_rowptr[N_NODES] = N_EDGES;
}

__global__ void build_csr_kernel(const void* e) {
    int i = blockIdx.x * blockDim.x + threadIdx.x;
    if (i < N_EDGES) {
        int is64 = g_is64;
        int s = load_edge(e, i, is64);
        int d = load_edge(e, (long long)N_EDGES + i, is64);
        int pos = g_rowptr[d] + atomicAdd(&g_fill[d], 1);
        g_adj[pos] = make_int2(s, __float_as_int(g_dinv[s]));
    }
}

// ---------------------------------------------------------------------------
// tf32x3 tensor-core GEMM: C[M,128] = A[M,128] @ W[128,128]
// Split A=Ahi+Alo, W=Whi+Wlo (tf32); accumulate hh + hl + lh in fp32.
// BM=128, BN=128 (full), BK=16, 256 threads (8 warps: 4(M) x 2(N)).
// Warp tile 32x64: 2 m16 tiles x 8 n8 tiles, mma.m16n8k8.
// ---------------------------------------------------------------------------
#define GBK 16
#define APAD 4   // A stride 20 -> conflict-free frag reads
#define BPAD 8   // B stride 136 -> conflict-free frag reads

__device__ __forceinline__ float tf32_rna(float a) {
    unsigned u;
    asm("cvt.rna.tf32.f32 %0, %1;" : "=r"(u) : "f"(a));
    return __uint_as_float(u);
}

__device__ __forceinline__ void mma_tf32(float c[4], const float a[4], const float b[2]) {
    const unsigned* A = reinterpret_cast<const unsigned*>(a);
    const unsigned* B = reinterpret_cast<const unsigned*>(b);
    asm volatile(
        "mma.sync.aligned.m16n8k8.row.col.f32.tf32.tf32.f32 "
        "{%0,%1,%2,%3}, {%4,%5,%6,%7}, {%8,%9}, {%0,%1,%2,%3};"
        : "+f"(c[0]), "+f"(c[1]), "+f"(c[2]), "+f"(c[3])
        : "r"(A[0]), "r"(A[1]), "r"(A[2]), "r"(A[3]), "r"(B[0]), "r"(B[1]));
}

__global__ __launch_bounds__(256) void gemm_tf32_kernel(
    const float* __restrict__ A, const float* __restrict__ W,
    float* __restrict__ C, int M)
{
    __shared__ float Ahi[128][GBK + APAD];
    __shared__ float Alo[128][GBK + APAD];
    __shared__ float Bhi[GBK][DIM + BPAD];
    __shared__ float Blo[GBK][DIM + BPAD];

    int tid = threadIdx.x;
    int warp = tid >> 5;
    int lane = tid & 31;
    int g = lane >> 2;        // groupID
    int t = lane & 3;         // threadID in group
    int wm = warp & 3;        // M warp (0..3), 32 rows each
    int wn = warp >> 2;       // N warp (0..1), 64 cols each
    int rowBase = blockIdx.x * 128;

    float c[2][8][4];
#pragma unroll
    for (int mt = 0; mt < 2; mt++)
#pragma unroll
        for (int j = 0; j < 8; j++)
#pragma unroll
            for (int e = 0; e < 4; e++) c[mt][j][e] = 0.0f;

    for (int kc = 0; kc < DIM / GBK; kc++) {
        int k0 = kc * GBK;
        // Load + split A tile (128 x 16): 512 float4, 2 per thread
#pragma unroll
        for (int i = 0; i < 2; i++) {
            int idx = tid + i * 256;
            int r = idx >> 2;
            int c4 = (idx & 3) * 4;
            float4 v = make_float4(0.f, 0.f, 0.f, 0.f);
            int grow = rowBase + r;
            if (grow < M) v = *(const float4*)&A[(size_t)grow * DIM + k0 + c4];
            float vv[4] = {v.x, v.y, v.z, v.w};
#pragma unroll
            for (int e = 0; e < 4; e++) {
                float hi = tf32_rna(vv[e]);
                Ahi[r][c4 + e] = hi;
                Alo[r][c4 + e] = tf32_rna(vv[e] - hi);
            }
        }
        // Load + split B tile (16 x 128): 512 float4, 2 per thread
#pragma unroll
        for (int i = 0; i < 2; i++) {
            int idx = tid + i * 256;
            int r = idx >> 5;
            int c4 = (idx & 31) * 4;
            float4 v = *(const float4*)&W[(size_t)(k0 + r) * DIM + c4];
            float vv[4] = {v.x, v.y, v.z, v.w};
#pragma unroll
            for (int e = 0; e < 4; e++) {
                float hi = tf32_rna(vv[e]);
                Bhi[r][c4 + e] = hi;
                Blo[r][c4 + e] = tf32_rna(vv[e] - hi);
            }
        }
        __syncthreads();

#pragma unroll
        for (int kk = 0; kk < GBK / 8; kk++) {
            int ks = kk * 8;
            float ahi[2][4], alo[2][4];
#pragma unroll
            for (int mt = 0; mt < 2; mt++) {
                int row = wm * 32 + mt * 16 + g;
                ahi[mt][0] = Ahi[row][ks + t];
                ahi[mt][1] = Ahi[row + 8][ks + t];
                ahi[mt][2] = Ahi[row][ks + t + 4];
                ahi[mt][3] = Ahi[row + 8][ks + t + 4];
                alo[mt][0] = Alo[row][ks + t];
                alo[mt][1] = Alo[row + 8][ks + t];
                alo[mt][2] = Alo[row][ks + t + 4];
                alo[mt][3] = Alo[row + 8][ks + t + 4];
            }
            float bhi[8][2], blo[8][2];
#pragma unroll
            for (int j = 0; j < 8; j++) {
                int n = wn * 64 + j * 8 + g;
                bhi[j][0] = Bhi[ks + t][n];
                bhi[j][1] = Bhi[ks + t + 4][n];
                blo[j][0] = Blo[ks + t][n];
                blo[j][1] = Blo[ks + t + 4][n];
            }
#pragma unroll
            for (int mt = 0; mt < 2; mt++)
#pragma unroll
                for (int j = 0; j < 8; j++) {
                    mma_tf32(c[mt][j], ahi[mt], bhi[j]);
                    mma_tf32(c[mt][j], ahi[mt], blo[j]);
                    mma_tf32(c[mt][j], alo[mt], bhi[j]);
                }
        }
        __syncthreads();
    }

    // Epilogue: c0,c1 -> (row, 2t..2t+1), c2,c3 -> (row+8, same)
#pragma unroll
    for (int mt = 0; mt < 2; mt++) {
        int r0 = rowBase + wm * 32 + mt * 16 + g;
        int r1 = r0 + 8;
#pragma unroll
        for (int j = 0; j < 8; j++) {
            int col = wn * 64 + j * 8 + 2 * t;
            if (r0 < M) *(float2*)&C[(size_t)r0 * DIM + col] = make_float2(c[mt][j][0], c[mt][j][1]);
            if (r1 < M) *(float2*)&C[(size_t)r1 * DIM + col] = make_float2(c[mt][j][2], c[mt][j][3]);
        }
    }
}

// ---------------------------------------------------------------------------
// Fused CSR gather + self loop + scale + bias + ReLU (warp per node)
// ---------------------------------------------------------------------------
__global__ __launch_bounds__(256) void gather_kernel(
    const float* __restrict__ h, const float* __restrict__ bias,
    float* __restrict__ out)
{
    int warp = (blockIdx.x * blockDim.x + threadIdx.x) >> 5;
    if (warp >= N_NODES) return;
    int lane = threadIdx.x & 31;
    int node = warp;
    int c = lane * 4;

    int start = g_rowptr[node];
    int end   = g_rowptr[node + 1];
    float dd  = g_dinv[node];

    float4 hv = *(const float4*)&h[(size_t)node * DIM + c];
    float4 acc = make_float4(dd * hv.x, dd * hv.y, dd * hv.z, dd * hv.w);

    for (int j = start; j < end; j += 32) {
        int idx = j + lane;
        int2 ew = make_int2(0, 0);
        if (idx < end) ew = g_adj[idx];
        int cnt = min(32, end - j);
#pragma unroll 8
        for (int k = 0; k < cnt; k++) {
            int   s = __shfl_sync(0xFFFFFFFFu, ew.x, k);
            float w = __int_as_float(__shfl_sync(0xFFFFFFFFu, ew.y, k));
            float4 v = *(const float4*)&h[(size_t)s * DIM + c];
            acc.x += w * v.x;
            acc.y += w * v.y;
            acc.z += w * v.z;
            acc.w += w * v.w;
        }
    }

    float4 b = *(const float4*)&bias[c];
    acc.x = fmaxf(dd * acc.x + b.x, 0.0f);
    acc.y = fmaxf(dd * acc.y + b.y, 0.0f);
    acc.z = fmaxf(dd * acc.z + b.z, 0.0f);
    acc.w = fmaxf(dd * acc.w + b.w, 0.0f);
    *(float4*)&out[(size_t)node * DIM + c] = acc;
}

// ---------------------------------------------------------------------------
// Launch
// ---------------------------------------------------------------------------
extern "C" void kernel_launch(void* const* d_in, const int* in_sizes, int n_in,
                              void* d_out, int out_size)
{
    const float* x       = (const float*)d_in[0];
    const void*  eidx    = d_in[1];
    const float* weights = (const float*)d_in[2];
    const float* biases  = (const float*)d_in[3];
    float*       out     = (float*)d_out;

    float* h;   cudaGetSymbolAddress((void**)&h,   g_h);
    float* acc; cudaGetSymbolAddress((void**)&acc, g_acc);

    // ---- Prologue: dtype detect, degrees, norm, two-level scan, CSR ----
    detect_dtype_kernel<<<1, 32>>>(eidx);
    zero_counts_kernel<<<SCAN_BLOCKS, 256>>>();
    hist_kernel<<<(N_EDGES + 255) / 256, 256>>>(eidx);
    dinv_kernel<<<SCAN_BLOCKS, 256>>>();
    scan1_kernel<<<SCAN_BLOCKS, 256>>>();
    scan2_kernel<<<1, 256>>>();
    scan3_kernel<<<SCAN_BLOCKS, 256>>>();
    build_csr_kernel<<<(N_EDGES + 255) / 256, 256>>>(eidx);

    const int gemm_blocks   = (N_NODES + 127) / 128;
    const int gather_blocks = (N_NODES * 32 + 255) / 256;

    const float* cur = x;
    for (int l = 0; l < N_LAYERS; l++) {
        const float* W = weights + (size_t)l * DIM * DIM;
        const float* b = biases + (size_t)l * DIM;
        float* layer_out = (l == N_LAYERS - 1) ? out : acc;

        gemm_tf32_kernel<<<gemm_blocks, 256>>>(cur, W, h, N_NODES);
        gather_kernel<<<gather_blocks, 256>>>(h, b, layer_out);

        cur = layer_out;
    }
}

// round 7
// speedup vs baseline: 1.2859x; 1.1490x over previous
#include <cuda_runtime.h>
#include <cuda_fp16.h>
#include <cstdint>

#define N_NODES 50000
#define N_EDGES 800000
#define DIM 128
#define N_LAYERS 5
#define SCAN_BLOCKS ((N_NODES + 255) / 256)   // 196

// ---------------------------------------------------------------------------
// Scratch (allocation-free rule: __device__ globals)
// ---------------------------------------------------------------------------
__device__ __half g_h[N_NODES * DIM];      // post-GEMM features (fp16)
__device__ __half g_act[N_NODES * DIM];    // layer activations (fp16)
__device__ int    g_count[N_NODES];
__device__ int    g_fill[N_NODES];
__device__ int    g_rowptr[N_NODES + 1];
__device__ float  g_dinv[N_NODES];
__device__ int2   g_adj[N_EDGES];          // (src, bitcast(dinv[src]))
__device__ int    g_is64;
__device__ int    g_blocksum[SCAN_BLOCKS];
__device__ int    g_blockoff[SCAN_BLOCKS];

// ---------------------------------------------------------------------------
// Edge dtype handling (int64 vs int32 storage)
// ---------------------------------------------------------------------------
__device__ __forceinline__ int load_edge(const void* e, long long idx, int is64) {
    if (is64) return (int)((const long long*)e)[idx];
    return ((const int*)e)[idx];
}

// fused: detect dtype + zero counters
__global__ void init_kernel(const void* e) {
    int i = blockIdx.x * blockDim.x + threadIdx.x;
    if (i < N_NODES) { g_count[i] = 0; g_fill[i] = 0; }
    if (blockIdx.x == 0 && threadIdx.x == 0) {
        const unsigned* w = (const unsigned*)e;
        int is64 = 1;
        for (int k = 0; k < 128; k++)
            if (w[2 * k + 1] != 0u) { is64 = 0; break; }
        g_is64 = is64;
    }
}

__global__ void hist_kernel(const void* e) {
    int i = blockIdx.x * blockDim.x + threadIdx.x;
    if (i < N_EDGES) {
        int d = load_edge(e, (long long)N_EDGES + i, g_is64);
        atomicAdd(&g_count[d], 1);
    }
}

// ---------------------------------------------------------------------------
// Two-level exclusive scan of g_count -> g_rowptr (dinv fused into pass 1)
// ---------------------------------------------------------------------------
__device__ __forceinline__ int warp_incl_scan(int x) {
#pragma unroll
    for (int o = 1; o < 32; o <<= 1) {
        int y = __shfl_up_sync(0xFFFFFFFFu, x, o);
        if ((threadIdx.x & 31) >= o) x += y;
    }
    return x;
}

__global__ void scan1_kernel() {
    __shared__ int wsum[8];
    int t = threadIdx.x, b = blockIdx.x;
    int i = b * 256 + t;
    int v = (i < N_NODES) ? g_count[i] : 0;
    if (i < N_NODES) g_dinv[i] = rsqrtf((float)(v + 1));  // fused dinv
    int x = warp_incl_scan(v);
    if ((t & 31) == 31) wsum[t >> 5] = x;
    __syncthreads();
    if (t == 0) {
        int run = 0;
#pragma unroll
        for (int w = 0; w < 8; w++) { int tmp = wsum[w]; wsum[w] = run; run += tmp; }
        g_blocksum[b] = run;
    }
    __syncthreads();
    if (i < N_NODES) g_rowptr[i] = x - v + wsum[t >> 5];  // exclusive, pre-offset
}

__global__ void scan2_kernel() {
    __shared__ int wsum[8];
    int t = threadIdx.x;
    int v = (t < SCAN_BLOCKS) ? g_blocksum[t] : 0;
    int x = warp_incl_scan(v);
    if ((t & 31) == 31) wsum[t >> 5] = x;
    __syncthreads();
    if (t == 0) {
        int run = 0;
#pragma unroll
        for (int w = 0; w < 8; w++) { int tmp = wsum[w]; wsum[w] = run; run += tmp; }
    }
    __syncthreads();
    if (t < SCAN_BLOCKS) g_blockoff[t] = x - v + wsum[t >> 5];
}

__global__ void scan3_kernel() {
    int i = blockIdx.x * blockDim.x + threadIdx.x;
    if (i < N_NODES) g_rowptr[i] += g_blockoff[i >> 8];
    if (i == 0) g_rowptr[N_NODES] = N_EDGES;
}

__global__ void build_csr_kernel(const void* e) {
    int i = blockIdx.x * blockDim.x + threadIdx.x;
    if (i < N_EDGES) {
        int is64 = g_is64;
        int s = load_edge(e, i, is64);
        int d = load_edge(e, (long long)N_EDGES + i, is64);
        int pos = g_rowptr[d] + atomicAdd(&g_fill[d], 1);
        g_adj[pos] = make_int2(s, __float_as_int(g_dinv[s]));
    }
}

// x (fp32) -> act (fp16)
__global__ void convert_x_kernel(const float* __restrict__ x, __half* __restrict__ act) {
    int i = blockIdx.x * blockDim.x + threadIdx.x;   // float4 index
    if (i < N_NODES * DIM / 4) {
        float4 v = *(const float4*)&x[i * 4];
        __half2 a = __floats2half2_rn(v.x, v.y);
        __half2 b = __floats2half2_rn(v.z, v.w);
        uint2 p = make_uint2(*(unsigned*)&a, *(unsigned*)&b);
        *(uint2*)&act[i * 4] = p;
    }
}

// ---------------------------------------------------------------------------
// fp16 tensor-core GEMM: C[M,128](fp16) = A[M,128](fp16) @ W[128,128](fp32)
// W split into fp16 hi+lo (22-bit mantissa coverage); 2x mma.m16n8k16 per step.
// BM=128, BN=128, BK=32, 256 threads (8 warps: 4(M) x 2(N)), warp tile 32x64.
// ---------------------------------------------------------------------------
#define GBK 32
#define SSTRIDE 40   // halves per smem row (32 + 8 pad) -> conflict-free frags

__device__ __forceinline__ void mma_fp16(float c[4], const unsigned a[4], const unsigned b[2]) {
    asm volatile(
        "mma.sync.aligned.m16n8k16.row.col.f32.f16.f16.f32 "
        "{%0,%1,%2,%3}, {%4,%5,%6,%7}, {%8,%9}, {%0,%1,%2,%3};"
        : "+f"(c[0]), "+f"(c[1]), "+f"(c[2]), "+f"(c[3])
        : "r"(a[0]), "r"(a[1]), "r"(a[2]), "r"(a[3]), "r"(b[0]), "r"(b[1]));
}

__global__ __launch_bounds__(256) void gemm_fp16_kernel(
    const __half* __restrict__ A, const float* __restrict__ W,
    __half* __restrict__ C, int M)
{
    __shared__ __half As [128][SSTRIDE];   // [m][k]
    __shared__ __half Bhi[128][SSTRIDE];   // [n][k] (transposed W, hi part)
    __shared__ __half Blo[128][SSTRIDE];   // [n][k] (lo part)

    int tid = threadIdx.x;
    int warp = tid >> 5;
    int lane = tid & 31;
    int g = lane >> 2;
    int t = lane & 3;
    int wm = warp & 3;       // M warp (32 rows)
    int wn = warp >> 2;      // N warp (64 cols)
    int rowBase = blockIdx.x * 128;

    float c[2][8][4];
#pragma unroll
    for (int mt = 0; mt < 2; mt++)
#pragma unroll
        for (int j = 0; j < 8; j++)
#pragma unroll
            for (int e = 0; e < 4; e++) c[mt][j][e] = 0.0f;

    for (int kc = 0; kc < DIM / GBK; kc++) {
        int k0 = kc * GBK;
        // A tile: 128 rows x 32 halves = 8KB. 512 x 16B loads, 2/thread.
#pragma unroll
        for (int i = 0; i < 2; i++) {
            int idx = tid + i * 256;
            int r = idx >> 2;             // row 0..127
            int part = idx & 3;           // 16B chunk (8 halves)
            uint4 v = make_uint4(0, 0, 0, 0);
            int grow = rowBase + r;
            if (grow < M) v = *(const uint4*)&A[(size_t)grow * DIM + k0 + part * 8];
            *(uint4*)&As[r][part * 8] = v;
        }
        // W tile: [32 k][128 n] fp32 -> split hi/lo fp16, store transposed [n][k].
#pragma unroll
        for (int i = 0; i < 4; i++) {
            int f4 = tid + i * 256;       // 1024 float4s
            int k = f4 >> 5;              // 0..31
            int n0 = (f4 & 31) * 4;
            float4 v = *(const float4*)&W[(size_t)(k0 + k) * DIM + n0];
            float vv[4] = {v.x, v.y, v.z, v.w};
#pragma unroll
            for (int e = 0; e < 4; e++) {
                __half hi = __float2half_rn(vv[e]);
                __half lo = __float2half_rn(vv[e] - __half2float(hi));
                Bhi[n0 + e][k] = hi;
                Blo[n0 + e][k] = lo;
            }
        }
        __syncthreads();

#pragma unroll
        for (int kk = 0; kk < GBK / 16; kk++) {
            int ks = kk * 16;
            unsigned a[2][4];
#pragma unroll
            for (int mt = 0; mt < 2; mt++) {
                int row = wm * 32 + mt * 16;
                a[mt][0] = *(const unsigned*)&As[row + g    ][ks + 2 * t];
                a[mt][1] = *(const unsigned*)&As[row + g + 8][ks + 2 * t];
                a[mt][2] = *(const unsigned*)&As[row + g    ][ks + 2 * t + 8];
                a[mt][3] = *(const unsigned*)&As[row + g + 8][ks + 2 * t + 8];
            }
#pragma unroll
            for (int j = 0; j < 8; j++) {
                int n = wn * 64 + j * 8 + g;
                unsigned bh[2], bl[2];
                bh[0] = *(const unsigned*)&Bhi[n][ks + 2 * t];
                bh[1] = *(const unsigned*)&Bhi[n][ks + 2 * t + 8];
                bl[0] = *(const unsigned*)&Blo[n][ks + 2 * t];
                bl[1] = *(const unsigned*)&Blo[n][ks + 2 * t + 8];
#pragma unroll
                for (int mt = 0; mt < 2; mt++) {
                    mma_fp16(c[mt][j], a[mt], bh);
                    mma_fp16(c[mt][j], a[mt], bl);
                }
            }
        }
        __syncthreads();
    }

    // Epilogue: fp32 accum -> fp16 store. c0,c1 -> (r0, 2t..2t+1); c2,c3 -> r0+8.
#pragma unroll
    for (int mt = 0; mt < 2; mt++) {
        int r0 = rowBase + wm * 32 + mt * 16 + g;
        int r1 = r0 + 8;
#pragma unroll
        for (int j = 0; j < 8; j++) {
            int col = wn * 64 + j * 8 + 2 * t;
            if (r0 < M) {
                __half2 p = __floats2half2_rn(c[mt][j][0], c[mt][j][1]);
                *(unsigned*)&C[(size_t)r0 * DIM + col] = *(unsigned*)&p;
            }
            if (r1 < M) {
                __half2 p = __floats2half2_rn(c[mt][j][2], c[mt][j][3]);
                *(unsigned*)&C[(size_t)r1 * DIM + col] = *(unsigned*)&p;
            }
        }
    }
}

// ---------------------------------------------------------------------------
// Fused CSR gather + self loop + scale + bias + ReLU (warp per node, fp16 h)
// out is fp16 (intermediate layers) or fp32 (final layer -> d_out)
// ---------------------------------------------------------------------------
__global__ __launch_bounds__(256) void gather_kernel(
    const __half* __restrict__ h, const float* __restrict__ bias,
    void* __restrict__ out, int out_half)
{
    int warp = (blockIdx.x * blockDim.x + threadIdx.x) >> 5;
    if (warp >= N_NODES) return;
    int lane = threadIdx.x & 31;
    int node = warp;
    int c = lane * 4;   // 4 columns per lane

    int start = g_rowptr[node];
    int end   = g_rowptr[node + 1];
    float dd  = g_dinv[node];

    // self-loop term: dinv[d] * h[d]
    uint2 sp = *(const uint2*)&h[(size_t)node * DIM + c];
    float2 s0 = __half22float2(*(__half2*)&sp.x);
    float2 s1 = __half22float2(*(__half2*)&sp.y);
    float4 acc = make_float4(dd * s0.x, dd * s0.y, dd * s1.x, dd * s1.y);

    for (int j = start; j < end; j += 32) {
        int idx = j + lane;
        int2 ew = make_int2(0, 0);
        if (idx < end) ew = g_adj[idx];
        int cnt = min(32, end - j);
#pragma unroll 8
        for (int k = 0; k < cnt; k++) {
            int   s = __shfl_sync(0xFFFFFFFFu, ew.x, k);
            float w = __int_as_float(__shfl_sync(0xFFFFFFFFu, ew.y, k));
            uint2 vp = *(const uint2*)&h[(size_t)s * DIM + c];
            float2 v0 = __half22float2(*(__half2*)&vp.x);
            float2 v1 = __half22float2(*(__half2*)&vp.y);
            acc.x += w * v0.x;
            acc.y += w * v0.y;
            acc.z += w * v1.x;
            acc.w += w * v1.y;
        }
    }

    float4 b = *(const float4*)&bias[c];
    acc.x = fmaxf(dd * acc.x + b.x, 0.0f);
    acc.y = fmaxf(dd * acc.y + b.y, 0.0f);
    acc.z = fmaxf(dd * acc.z + b.z, 0.0f);
    acc.w = fmaxf(dd * acc.w + b.w, 0.0f);

    if (out_half) {
        __half2 p0 = __floats2half2_rn(acc.x, acc.y);
        __half2 p1 = __floats2half2_rn(acc.z, acc.w);
        uint2 p = make_uint2(*(unsigned*)&p0, *(unsigned*)&p1);
        *(uint2*)&((__half*)out)[(size_t)node * DIM + c] = p;
    } else {
        *(float4*)&((float*)out)[(size_t)node * DIM + c] = acc;
    }
}

// ---------------------------------------------------------------------------
// Launch
// ---------------------------------------------------------------------------
extern "C" void kernel_launch(void* const* d_in, const int* in_sizes, int n_in,
                              void* d_out, int out_size)
{
    const float* x       = (const float*)d_in[0];
    const void*  eidx    = d_in[1];
    const float* weights = (const float*)d_in[2];
    const float* biases  = (const float*)d_in[3];
    float*       out     = (float*)d_out;

    __half* h;   cudaGetSymbolAddress((void**)&h,   g_h);
    __half* act; cudaGetSymbolAddress((void**)&act, g_act);

    // ---- Prologue ----
    init_kernel<<<SCAN_BLOCKS, 256>>>(eidx);
    hist_kernel<<<(N_EDGES + 255) / 256, 256>>>(eidx);
    scan1_kernel<<<SCAN_BLOCKS, 256>>>();
    scan2_kernel<<<1, 256>>>();
    scan3_kernel<<<SCAN_BLOCKS, 256>>>();
    build_csr_kernel<<<(N_EDGES + 255) / 256, 256>>>(eidx);
    convert_x_kernel<<<(N_NODES * DIM / 4 + 255) / 256, 256>>>(x, act);

    const int gemm_blocks   = (N_NODES + 127) / 128;
    const int gather_blocks = (N_NODES * 32 + 255) / 256;

    for (int l = 0; l < N_LAYERS; l++) {
        const float* W = weights + (size_t)l * DIM * DIM;
        const float* b = biases + (size_t)l * DIM;
        int last = (l == N_LAYERS - 1);

        gemm_fp16_kernel<<<gemm_blocks, 256>>>(act, W, h, N_NODES);
        gather_kernel<<<gather_blocks, 256>>>(h, b, last ? (void*)out : (void*)act, !last);
    }
}

// round 8
// speedup vs baseline: 1.3443x; 1.0455x over previous
#include <cuda_runtime.h>
#include <cuda_fp16.h>
#include <cstdint>

#define N_NODES 50000
#define N_EDGES 800000
#define DIM 128
#define N_LAYERS 5
#define SCAN_BLOCKS ((N_NODES + 255) / 256)   // 196

// ---------------------------------------------------------------------------
// Scratch (allocation-free rule: __device__ globals)
// ---------------------------------------------------------------------------
__device__ __half g_h[N_NODES * DIM];      // post-GEMM features (fp16)
__device__ __half g_act[N_NODES * DIM];    // layer activations (fp16)
__device__ int    g_count[N_NODES];
__device__ int    g_fill[N_NODES];
__device__ int    g_rowptr[N_NODES + 1];
__device__ float  g_dinv[N_NODES];
__device__ int2   g_adj[N_EDGES];          // (src, bitcast(dinv[src]))
__device__ int    g_is64;
__device__ int    g_blocksum[SCAN_BLOCKS];
__device__ int    g_blockoff[SCAN_BLOCKS];

// ---------------------------------------------------------------------------
// Edge dtype handling (int64 vs int32 storage)
// ---------------------------------------------------------------------------
__device__ __forceinline__ int load_edge(const void* e, long long idx, int is64) {
    if (is64) return (int)((const long long*)e)[idx];
    return ((const int*)e)[idx];
}

// fused: detect dtype + zero counters
__global__ void init_kernel(const void* e) {
    int i = blockIdx.x * blockDim.x + threadIdx.x;
    if (i < N_NODES) { g_count[i] = 0; g_fill[i] = 0; }
    if (blockIdx.x == 0 && threadIdx.x == 0) {
        const unsigned* w = (const unsigned*)e;
        int is64 = 1;
        for (int k = 0; k < 128; k++)
            if (w[2 * k + 1] != 0u) { is64 = 0; break; }
        g_is64 = is64;
    }
}

__global__ void hist_kernel(const void* e) {
    int i = blockIdx.x * blockDim.x + threadIdx.x;
    if (i < N_EDGES) {
        int d = load_edge(e, (long long)N_EDGES + i, g_is64);
        atomicAdd(&g_count[d], 1);
    }
}

// ---------------------------------------------------------------------------
// Two-level exclusive scan of g_count -> g_rowptr (dinv fused into pass 1)
// ---------------------------------------------------------------------------
__device__ __forceinline__ int warp_incl_scan(int x) {
#pragma unroll
    for (int o = 1; o < 32; o <<= 1) {
        int y = __shfl_up_sync(0xFFFFFFFFu, x, o);
        if ((threadIdx.x & 31) >= o) x += y;
    }
    return x;
}

__global__ void scan1_kernel() {
    __shared__ int wsum[8];
    int t = threadIdx.x, b = blockIdx.x;
    int i = b * 256 + t;
    int v = (i < N_NODES) ? g_count[i] : 0;
    if (i < N_NODES) g_dinv[i] = rsqrtf((float)(v + 1));  // fused dinv
    int x = warp_incl_scan(v);
    if ((t & 31) == 31) wsum[t >> 5] = x;
    __syncthreads();
    if (t == 0) {
        int run = 0;
#pragma unroll
        for (int w = 0; w < 8; w++) { int tmp = wsum[w]; wsum[w] = run; run += tmp; }
        g_blocksum[b] = run;
    }
    __syncthreads();
    if (i < N_NODES) g_rowptr[i] = x - v + wsum[t >> 5];  // exclusive, pre-offset
}

__global__ void scan2_kernel() {
    __shared__ int wsum[8];
    int t = threadIdx.x;
    int v = (t < SCAN_BLOCKS) ? g_blocksum[t] : 0;
    int x = warp_incl_scan(v);
    if ((t & 31) == 31) wsum[t >> 5] = x;
    __syncthreads();
    if (t == 0) {
        int run = 0;
#pragma unroll
        for (int w = 0; w < 8; w++) { int tmp = wsum[w]; wsum[w] = run; run += tmp; }
    }
    __syncthreads();
    if (t < SCAN_BLOCKS) g_blockoff[t] = x - v + wsum[t >> 5];
}

__global__ void scan3_kernel() {
    int i = blockIdx.x * blockDim.x + threadIdx.x;
    if (i < N_NODES) g_rowptr[i] += g_blockoff[i >> 8];
    if (i == 0) g_rowptr[N_NODES] = N_EDGES;
}

__global__ void build_csr_kernel(const void* e) {
    int i = blockIdx.x * blockDim.x + threadIdx.x;
    if (i < N_EDGES) {
        int is64 = g_is64;
        int s = load_edge(e, i, is64);
        int d = load_edge(e, (long long)N_EDGES + i, is64);
        int pos = g_rowptr[d] + atomicAdd(&g_fill[d], 1);
        g_adj[pos] = make_int2(s, __float_as_int(g_dinv[s]));
    }
}

// x (fp32) -> act (fp16)
__global__ void convert_x_kernel(const float* __restrict__ x, __half* __restrict__ act) {
    int i = blockIdx.x * blockDim.x + threadIdx.x;   // float4 index
    if (i < N_NODES * DIM / 4) {
        float4 v = *(const float4*)&x[i * 4];
        __half2 a = __floats2half2_rn(v.x, v.y);
        __half2 b = __floats2half2_rn(v.z, v.w);
        uint2 p = make_uint2(*(unsigned*)&a, *(unsigned*)&b);
        *(uint2*)&act[i * 4] = p;
    }
}

// ---------------------------------------------------------------------------
// fp16 tensor-core GEMM: C[M,128](fp16) = A[M,128](fp16) @ W[128,128](fp32)
// W split into fp16 hi+lo (22-bit mantissa coverage); 2x mma.m16n8k16 per step.
// BM=128, BN=128, BK=32, 256 threads (8 warps: 4(M) x 2(N)), warp tile 32x64.
// ---------------------------------------------------------------------------
#define GBK 32
#define SSTRIDE 40   // halves per smem row (32 + 8 pad) -> conflict-free frags

__device__ __forceinline__ void mma_fp16(float c[4], const unsigned a[4], const unsigned b[2]) {
    asm volatile(
        "mma.sync.aligned.m16n8k16.row.col.f32.f16.f16.f32 "
        "{%0,%1,%2,%3}, {%4,%5,%6,%7}, {%8,%9}, {%0,%1,%2,%3};"
        : "+f"(c[0]), "+f"(c[1]), "+f"(c[2]), "+f"(c[3])
        : "r"(a[0]), "r"(a[1]), "r"(a[2]), "r"(a[3]), "r"(b[0]), "r"(b[1]));
}

__global__ __launch_bounds__(256) void gemm_fp16_kernel(
    const __half* __restrict__ A, const float* __restrict__ W,
    __half* __restrict__ C, int M)
{
    __shared__ __half As [128][SSTRIDE];   // [m][k]
    __shared__ __half Bhi[128][SSTRIDE];   // [n][k] (transposed W, hi part)
    __shared__ __half Blo[128][SSTRIDE];   // [n][k] (lo part)

    int tid = threadIdx.x;
    int warp = tid >> 5;
    int lane = tid & 31;
    int g = lane >> 2;
    int t = lane & 3;
    int wm = warp & 3;       // M warp (32 rows)
    int wn = warp >> 2;      // N warp (64 cols)
    int rowBase = blockIdx.x * 128;

    float c[2][8][4];
#pragma unroll
    for (int mt = 0; mt < 2; mt++)
#pragma unroll
        for (int j = 0; j < 8; j++)
#pragma unroll
            for (int e = 0; e < 4; e++) c[mt][j][e] = 0.0f;

    for (int kc = 0; kc < DIM / GBK; kc++) {
        int k0 = kc * GBK;
        // A tile: 128 rows x 32 halves = 8KB. 512 x 16B loads, 2/thread.
#pragma unroll
        for (int i = 0; i < 2; i++) {
            int idx = tid + i * 256;
            int r = idx >> 2;             // row 0..127
            int part = idx & 3;           // 16B chunk (8 halves)
            uint4 v = make_uint4(0, 0, 0, 0);
            int grow = rowBase + r;
            if (grow < M) v = *(const uint4*)&A[(size_t)grow * DIM + k0 + part * 8];
            *(uint4*)&As[r][part * 8] = v;
        }
        // W tile: [32 k][128 n] fp32 -> split hi/lo fp16, store transposed [n][k].
#pragma unroll
        for (int i = 0; i < 4; i++) {
            int f4 = tid + i * 256;       // 1024 float4s
            int k = f4 >> 5;              // 0..31
            int n0 = (f4 & 31) * 4;
            float4 v = *(const float4*)&W[(size_t)(k0 + k) * DIM + n0];
            float vv[4] = {v.x, v.y, v.z, v.w};
#pragma unroll
            for (int e = 0; e < 4; e++) {
                __half hi = __float2half_rn(vv[e]);
                __half lo = __float2half_rn(vv[e] - __half2float(hi));
                Bhi[n0 + e][k] = hi;
                Blo[n0 + e][k] = lo;
            }
        }
        __syncthreads();

#pragma unroll
        for (int kk = 0; kk < GBK / 16; kk++) {
            int ks = kk * 16;
            unsigned a[2][4];
#pragma unroll
            for (int mt = 0; mt < 2; mt++) {
                int row = wm * 32 + mt * 16;
                a[mt][0] = *(const unsigned*)&As[row + g    ][ks + 2 * t];
                a[mt][1] = *(const unsigned*)&As[row + g + 8][ks + 2 * t];
                a[mt][2] = *(const unsigned*)&As[row + g    ][ks + 2 * t + 8];
                a[mt][3] = *(const unsigned*)&As[row + g + 8][ks + 2 * t + 8];
            }
#pragma unroll
            for (int j = 0; j < 8; j++) {
                int n = wn * 64 + j * 8 + g;
                unsigned bh[2], bl[2];
                bh[0] = *(const unsigned*)&Bhi[n][ks + 2 * t];
                bh[1] = *(const unsigned*)&Bhi[n][ks + 2 * t + 8];
                bl[0] = *(const unsigned*)&Blo[n][ks + 2 * t];
                bl[1] = *(const unsigned*)&Blo[n][ks + 2 * t + 8];
#pragma unroll
                for (int mt = 0; mt < 2; mt++) {
                    mma_fp16(c[mt][j], a[mt], bh);
                    mma_fp16(c[mt][j], a[mt], bl);
                }
            }
        }
        __syncthreads();
    }

    // Epilogue: fp32 accum -> fp16 store. c0,c1 -> (r0, 2t..2t+1); c2,c3 -> r0+8.
#pragma unroll
    for (int mt = 0; mt < 2; mt++) {
        int r0 = rowBase + wm * 32 + mt * 16 + g;
        int r1 = r0 + 8;
#pragma unroll
        for (int j = 0; j < 8; j++) {
            int col = wn * 64 + j * 8 + 2 * t;
            if (r0 < M) {
                __half2 p = __floats2half2_rn(c[mt][j][0], c[mt][j][1]);
                *(unsigned*)&C[(size_t)r0 * DIM + col] = *(unsigned*)&p;
            }
            if (r1 < M) {
                __half2 p = __floats2half2_rn(c[mt][j][2], c[mt][j][3]);
                *(unsigned*)&C[(size_t)r1 * DIM + col] = *(unsigned*)&p;
            }
        }
    }
}

// ---------------------------------------------------------------------------
// Fused CSR gather + self loop + scale + bias + ReLU.
// Warp per node, HALF-WARP per edge: lanes 0-15 even edges, 16-31 odd edges.
// Each lane covers 8 halves (uint4 = 16B) of the 256B row. Adjacency read as
// uniform broadcast load (no shfl). Cross-half reduction once at the end.
// ---------------------------------------------------------------------------
__global__ __launch_bounds__(256) void gather_kernel(
    const __half* __restrict__ h, const float* __restrict__ bias,
    void* __restrict__ out, int out_half)
{
    int warp = (blockIdx.x * blockDim.x + threadIdx.x) >> 5;
    if (warp >= N_NODES) return;
    int lane = threadIdx.x & 31;
    int g16 = lane >> 4;     // half-warp id (0: even edges, 1: odd edges)
    int l16 = lane & 15;
    int node = warp;
    int c = l16 * 8;         // 8 consecutive halves per lane

    int start = g_rowptr[node];
    int end   = g_rowptr[node + 1];
    float dd  = g_dinv[node];

    float acc[8];
    // Self-loop term handled by half 0 only (avoid double count).
    {
        uint4 p = *(const uint4*)&h[(size_t)node * DIM + c];
        const __half2* hp = (const __half2*)&p;
        float w0 = g16 ? 0.0f : dd;
#pragma unroll
        for (int i = 0; i < 4; i++) {
            float2 f = __half22float2(hp[i]);
            acc[2 * i]     = w0 * f.x;
            acc[2 * i + 1] = w0 * f.y;
        }
    }

#pragma unroll 4
    for (int j = start + g16; j < end; j += 2) {
        int2 ew = g_adj[j];                       // uniform within half-warp -> broadcast
        float w = __int_as_float(ew.y);
        uint4 p = *(const uint4*)&h[(size_t)ew.x * DIM + c];
        const __half2* hp = (const __half2*)&p;
#pragma unroll
        for (int i = 0; i < 4; i++) {
            float2 f = __half22float2(hp[i]);
            acc[2 * i]     += w * f.x;
            acc[2 * i + 1] += w * f.y;
        }
    }

    // Combine the two half-warp partial sums (columns align across halves).
#pragma unroll
    for (int i = 0; i < 8; i++)
        acc[i] += __shfl_xor_sync(0xFFFFFFFFu, acc[i], 16);

    if (g16 == 0) {
        float4 b0 = *(const float4*)&bias[c];
        float4 b1 = *(const float4*)&bias[c + 4];
        float r[8];
        r[0] = fmaxf(dd * acc[0] + b0.x, 0.0f);
        r[1] = fmaxf(dd * acc[1] + b0.y, 0.0f);
        r[2] = fmaxf(dd * acc[2] + b0.z, 0.0f);
        r[3] = fmaxf(dd * acc[3] + b0.w, 0.0f);
        r[4] = fmaxf(dd * acc[4] + b1.x, 0.0f);
        r[5] = fmaxf(dd * acc[5] + b1.y, 0.0f);
        r[6] = fmaxf(dd * acc[6] + b1.z, 0.0f);
        r[7] = fmaxf(dd * acc[7] + b1.w, 0.0f);

        if (out_half) {
            __half2 p0 = __floats2half2_rn(r[0], r[1]);
            __half2 p1 = __floats2half2_rn(r[2], r[3]);
            __half2 p2 = __floats2half2_rn(r[4], r[5]);
            __half2 p3 = __floats2half2_rn(r[6], r[7]);
            uint4 pk = make_uint4(*(unsigned*)&p0, *(unsigned*)&p1,
                                  *(unsigned*)&p2, *(unsigned*)&p3);
            *(uint4*)&((__half*)out)[(size_t)node * DIM + c] = pk;
        } else {
            float* o = (float*)out + (size_t)node * DIM + c;
            *(float4*)&o[0] = make_float4(r[0], r[1], r[2], r[3]);
            *(float4*)&o[4] = make_float4(r[4], r[5], r[6], r[7]);
        }
    }
}

// ---------------------------------------------------------------------------
// Launch
// ---------------------------------------------------------------------------
extern "C" void kernel_launch(void* const* d_in, const int* in_sizes, int n_in,
                              void* d_out, int out_size)
{
    const float* x       = (const float*)d_in[0];
    const void*  eidx    = d_in[1];
    const float* weights = (const float*)d_in[2];
    const float* biases  = (const float*)d_in[3];
    float*       out     = (float*)d_out;

    __half* h;   cudaGetSymbolAddress((void**)&h,   g_h);
    __half* act; cudaGetSymbolAddress((void**)&act, g_act);

    // ---- Prologue ----
    init_kernel<<<SCAN_BLOCKS, 256>>>(eidx);
    hist_kernel<<<(N_EDGES + 255) / 256, 256>>>(eidx);
    scan1_kernel<<<SCAN_BLOCKS, 256>>>();
    scan2_kernel<<<1, 256>>>();
    scan3_kernel<<<SCAN_BLOCKS, 256>>>();
    build_csr_kernel<<<(N_EDGES + 255) / 256, 256>>>(eidx);
    convert_x_kernel<<<(N_NODES * DIM / 4 + 255) / 256, 256>>>(x, act);

    const int gemm_blocks   = (N_NODES + 127) / 128;
    const int gather_blocks = (N_NODES * 32 + 255) / 256;

    for (int l = 0; l < N_LAYERS; l++) {
        const float* W = weights + (size_t)l * DIM * DIM;
        const float* b = biases + (size_t)l * DIM;
        int last = (l == N_LAYERS - 1);

        gemm_fp16_kernel<<<gemm_blocks, 256>>>(act, W, h, N_NODES);
        gather_kernel<<<gather_blocks, 256>>>(h, b, last ? (void*)out : (void*)act, !last);
    }
}

// round 9
// speedup vs baseline: 1.4930x; 1.1106x over previous
#include <cuda_runtime.h>
#include <cuda_fp16.h>
#include <cstdint>

#define N_NODES 50000
#define N_EDGES 800000
#define DIM 128
#define N_LAYERS 5
#define SCAN_BLOCKS ((N_NODES + 255) / 256)   // 196
#define N_F4 (N_NODES * DIM / 4)              // 1,600,000 (= 2 * N_EDGES)

// ---------------------------------------------------------------------------
// Scratch (allocation-free rule: __device__ globals)
// ---------------------------------------------------------------------------
__device__ __half g_h[N_NODES * DIM];      // post-GEMM features (fp16)
__device__ __half g_act[N_NODES * DIM];    // layer activations (fp16)
__device__ int    g_count[N_NODES];
__device__ int    g_fill[N_NODES];
__device__ int    g_rowptr[N_NODES + 1];
__device__ float  g_dinv[N_NODES];
__device__ int2   g_adj[N_EDGES];          // (src, bitcast(dinv[src]))
__device__ int    g_is64;
__device__ int    g_blocksum[SCAN_BLOCKS];
__device__ int    g_scanflag[SCAN_BLOCKS];

// ---------------------------------------------------------------------------
// Edge dtype handling (int64 vs int32 storage)
// ---------------------------------------------------------------------------
__device__ __forceinline__ int load_edge(const void* e, long long idx, int is64) {
    if (is64) return (int)((const long long*)e)[idx];
    return ((const int*)e)[idx];
}

// fused: detect dtype + zero counters + zero scan flags
__global__ void init_kernel(const void* e) {
    int i = blockIdx.x * blockDim.x + threadIdx.x;
    if (i < N_NODES) { g_count[i] = 0; g_fill[i] = 0; }
    if (i < SCAN_BLOCKS) g_scanflag[i] = 0;
    if (blockIdx.x == 0 && threadIdx.x == 0) {
        const unsigned* w = (const unsigned*)e;
        int is64 = 1;
        for (int k = 0; k < 128; k++)
            if (w[2 * k + 1] != 0u) { is64 = 0; break; }
        g_is64 = is64;
    }
}

// 2 edges per thread, vectorized dst loads (N_EDGES is even)
__global__ void hist_kernel(const void* e) {
    int i = blockIdx.x * blockDim.x + threadIdx.x;   // pair index
    if (2 * i >= N_EDGES) return;
    if (g_is64) {
        longlong2 p = ((const longlong2*)e)[(N_EDGES + 2 * i) >> 1];
        atomicAdd(&g_count[(int)p.x], 1);
        atomicAdd(&g_count[(int)p.y], 1);
    } else {
        int2 p = ((const int2*)e)[(N_EDGES + 2 * i) >> 1];
        atomicAdd(&g_count[p.x], 1);
        atomicAdd(&g_count[p.y], 1);
    }
}

// ---------------------------------------------------------------------------
// Single-kernel exclusive scan (publish-then-spin decoupled lookback)
// + fused dinv. 196 blocks, all co-resident -> no deadlock.
// ---------------------------------------------------------------------------
__device__ __forceinline__ int warp_incl_scan(int x) {
#pragma unroll
    for (int o = 1; o < 32; o <<= 1) {
        int y = __shfl_up_sync(0xFFFFFFFFu, x, o);
        if ((threadIdx.x & 31) >= o) x += y;
    }
    return x;
}

__global__ void scan_kernel() {
    __shared__ int wsum[8];
    __shared__ int sh_off;
    int t = threadIdx.x, b = blockIdx.x;
    int i = b * 256 + t;
    int v = (i < N_NODES) ? g_count[i] : 0;
    if (i < N_NODES) g_dinv[i] = rsqrtf((float)(v + 1));  // fused dinv
    int x = warp_incl_scan(v);
    if ((t & 31) == 31) wsum[t >> 5] = x;
    if (t == 0) sh_off = 0;
    __syncthreads();
    if (t == 0) {
        int run = 0;
#pragma unroll
        for (int w = 0; w < 8; w++) { int tmp = wsum[w]; wsum[w] = run; run += tmp; }
        // publish this block's total BEFORE any waiting
        g_blocksum[b] = run;
        __threadfence();
        atomicExch(&g_scanflag[b], 1);
    }
    __syncthreads();
    // parallel lookback: thread t handles predecessor t (196 < 256)
    if (t < b) {
        while (atomicAdd(&g_scanflag[t], 0) == 0) { }
        atomicAdd(&sh_off, g_blocksum[t]);
    }
    __syncthreads();
    if (i < N_NODES) g_rowptr[i] = sh_off + x - v + wsum[t >> 5];
    if (i == 0) g_rowptr[N_NODES] = N_EDGES;
}

// build CSR adjacency + fused x(fp32)->act(fp16) conversion
__global__ void build_csr_kernel(const void* e, const float* __restrict__ x,
                                 __half* __restrict__ act) {
    int i = blockIdx.x * blockDim.x + threadIdx.x;
    if (i < N_EDGES) {
        int is64 = g_is64;
        int s = load_edge(e, i, is64);
        int d = load_edge(e, (long long)N_EDGES + i, is64);
        int pos = g_rowptr[d] + atomicAdd(&g_fill[d], 1);
        g_adj[pos] = make_int2(s, __float_as_int(g_dinv[s]));
    }
    // fp16 convert: exactly 2 float4s per thread (N_F4 == 2*N_EDGES)
#pragma unroll
    for (int v4 = i; v4 < N_F4; v4 += N_EDGES) {
        float4 v = *(const float4*)&x[(size_t)v4 * 4];
        __half2 a = __floats2half2_rn(v.x, v.y);
        __half2 b = __floats2half2_rn(v.z, v.w);
        uint2 p = make_uint2(*(unsigned*)&a, *(unsigned*)&b);
        *(uint2*)&act[(size_t)v4 * 4] = p;
    }
}

// ---------------------------------------------------------------------------
// fp16 tensor-core GEMM with FULL W resident in dynamic smem (split once).
// C[M,128](fp16) = A[M,128](fp16) @ W[128,128](fp32), W = hi+lo fp16.
// Grid-stride over 128-row tiles; 256 threads (8 warps: 4(M) x 2(N)).
// ---------------------------------------------------------------------------
#define WSTR 136   // halves per W smem row (128 + 8 pad)
#define ASTR 40    // halves per A smem row (32 + 8 pad)
#define GEMM_SMEM ((2 * 128 * WSTR + 128 * ASTR) * 2)   // 79,872 B
#define N_TILES ((N_NODES + 127) / 128)                  // 391
#define GEMM_GRID 296                                    // 2 blocks/SM

__device__ __forceinline__ void mma_fp16(float c[4], const unsigned a[4], const unsigned b[2]) {
    asm volatile(
        "mma.sync.aligned.m16n8k16.row.col.f32.f16.f16.f32 "
        "{%0,%1,%2,%3}, {%4,%5,%6,%7}, {%8,%9}, {%0,%1,%2,%3};"
        : "+f"(c[0]), "+f"(c[1]), "+f"(c[2]), "+f"(c[3])
        : "r"(a[0]), "r"(a[1]), "r"(a[2]), "r"(a[3]), "r"(b[0]), "r"(b[1]));
}

__global__ __launch_bounds__(256) void gemm_fp16_kernel(
    const __half* __restrict__ A, const float* __restrict__ W,
    __half* __restrict__ C, int M)
{
    extern __shared__ __half smem[];
    __half (*Bhi)[WSTR] = (__half(*)[WSTR])smem;                  // [n][k]
    __half (*Blo)[WSTR] = (__half(*)[WSTR])(smem + 128 * WSTR);
    __half (*As)[ASTR]  = (__half(*)[ASTR])(smem + 2 * 128 * WSTR);

    int tid = threadIdx.x;
    int warp = tid >> 5;
    int lane = tid & 31;
    int g = lane >> 2;
    int t = lane & 3;
    int wm = warp & 3;       // M warp (32 rows)
    int wn = warp >> 2;      // N warp (64 cols)

    // ---- Load + split FULL W once: 4096 float4s, 16 per thread ----
#pragma unroll
    for (int i = 0; i < 16; i++) {
        int f4 = tid + i * 256;
        int k = f4 >> 5;              // 0..127
        int n0 = (f4 & 31) * 4;
        float4 v = *(const float4*)&W[(size_t)k * DIM + n0];
        float vv[4] = {v.x, v.y, v.z, v.w};
#pragma unroll
        for (int e = 0; e < 4; e++) {
            __half hi = __float2half_rn(vv[e]);
            __half lo = __float2half_rn(vv[e] - __half2float(hi));
            Bhi[n0 + e][k] = hi;
            Blo[n0 + e][k] = lo;
        }
    }
    __syncthreads();

    for (int tile = blockIdx.x; tile < N_TILES; tile += gridDim.x) {
        int rowBase = tile * 128;

        float c[2][8][4];
#pragma unroll
        for (int mt = 0; mt < 2; mt++)
#pragma unroll
            for (int j = 0; j < 8; j++)
#pragma unroll
                for (int e = 0; e < 4; e++) c[mt][j][e] = 0.0f;

        for (int kc = 0; kc < 4; kc++) {
            int k0 = kc * 32;
            // A tile: 128 rows x 32 halves. 512 x 16B loads, 2/thread.
#pragma unroll
            for (int i = 0; i < 2; i++) {
                int idx = tid + i * 256;
                int r = idx >> 2;
                int part = idx & 3;
                uint4 v = make_uint4(0, 0, 0, 0);
                int grow = rowBase + r;
                if (grow < M) v = *(const uint4*)&A[(size_t)grow * DIM + k0 + part * 8];
                *(uint4*)&As[r][part * 8] = v;
            }
            __syncthreads();

#pragma unroll
            for (int kk = 0; kk < 2; kk++) {
                int ks = kk * 16;          // within As chunk
                int ksg = k0 + ks;         // global k for W
                unsigned a[2][4];
#pragma unroll
                for (int mt = 0; mt < 2; mt++) {
                    int row = wm * 32 + mt * 16;
                    a[mt][0] = *(const unsigned*)&As[row + g    ][ks + 2 * t];
                    a[mt][1] = *(const unsigned*)&As[row + g + 8][ks + 2 * t];
                    a[mt][2] = *(const unsigned*)&As[row + g    ][ks + 2 * t + 8];
                    a[mt][3] = *(const unsigned*)&As[row + g + 8][ks + 2 * t + 8];
                }
#pragma unroll
                for (int j = 0; j < 8; j++) {
                    int n = wn * 64 + j * 8 + g;
                    unsigned bh[2], bl[2];
                    bh[0] = *(const unsigned*)&Bhi[n][ksg + 2 * t];
                    bh[1] = *(const unsigned*)&Bhi[n][ksg + 2 * t + 8];
                    bl[0] = *(const unsigned*)&Blo[n][ksg + 2 * t];
                    bl[1] = *(const unsigned*)&Blo[n][ksg + 2 * t + 8];
#pragma unroll
                    for (int mt = 0; mt < 2; mt++) {
                        mma_fp16(c[mt][j], a[mt], bh);
                        mma_fp16(c[mt][j], a[mt], bl);
                    }
                }
            }
            __syncthreads();
        }

        // Epilogue: fp32 accum -> fp16 store
#pragma unroll
        for (int mt = 0; mt < 2; mt++) {
            int r0 = rowBase + wm * 32 + mt * 16 + g;
            int r1 = r0 + 8;
#pragma unroll
            for (int j = 0; j < 8; j++) {
                int col = wn * 64 + j * 8 + 2 * t;
                if (r0 < M) {
                    __half2 p = __floats2half2_rn(c[mt][j][0], c[mt][j][1]);
                    *(unsigned*)&C[(size_t)r0 * DIM + col] = *(unsigned*)&p;
                }
                if (r1 < M) {
                    __half2 p = __floats2half2_rn(c[mt][j][2], c[mt][j][3]);
                    *(unsigned*)&C[(size_t)r1 * DIM + col] = *(unsigned*)&p;
                }
            }
        }
    }
}

// ---------------------------------------------------------------------------
// Fused CSR gather + self loop + scale + bias + ReLU.
// Warp per node, HALF-WARP per edge; row loads via __ldcg (L2-resident data).
// ---------------------------------------------------------------------------
__global__ __launch_bounds__(256) void gather_kernel(
    const __half* __restrict__ h, const float* __restrict__ bias,
    void* __restrict__ out, int out_half)
{
    int warp = (blockIdx.x * blockDim.x + threadIdx.x) >> 5;
    if (warp >= N_NODES) return;
    int lane = threadIdx.x & 31;
    int g16 = lane >> 4;     // half-warp id (0: even edges, 1: odd edges)
    int l16 = lane & 15;
    int node = warp;
    int c = l16 * 8;         // 8 consecutive halves per lane

    int start = g_rowptr[node];
    int end   = g_rowptr[node + 1];
    float dd  = g_dinv[node];

    float acc[8];
    {
        uint4 p = __ldcg((const uint4*)&h[(size_t)node * DIM + c]);
        const __half2* hp = (const __half2*)&p;
        float w0 = g16 ? 0.0f : dd;   // self loop counted once
#pragma unroll
        for (int i = 0; i < 4; i++) {
            float2 f = __half22float2(hp[i]);
            acc[2 * i]     = w0 * f.x;
            acc[2 * i + 1] = w0 * f.y;
        }
    }

#pragma unroll 8
    for (int j = start + g16; j < end; j += 2) {
        int2 ew = g_adj[j];                       // uniform in half-warp -> broadcast
        float w = __int_as_float(ew.y);
        uint4 p = __ldcg((const uint4*)&h[(size_t)ew.x * DIM + c]);
        const __half2* hp = (const __half2*)&p;
#pragma unroll
        for (int i = 0; i < 4; i++) {
            float2 f = __half22float2(hp[i]);
            acc[2 * i]     += w * f.x;
            acc[2 * i + 1] += w * f.y;
        }
    }

#pragma unroll
    for (int i = 0; i < 8; i++)
        acc[i] += __shfl_xor_sync(0xFFFFFFFFu, acc[i], 16);

    if (g16 == 0) {
        float4 b0 = *(const float4*)&bias[c];
        float4 b1 = *(const float4*)&bias[c + 4];
        float r[8];
        r[0] = fmaxf(dd * acc[0] + b0.x, 0.0f);
        r[1] = fmaxf(dd * acc[1] + b0.y, 0.0f);
        r[2] = fmaxf(dd * acc[2] + b0.z, 0.0f);
        r[3] = fmaxf(dd * acc[3] + b0.w, 0.0f);
        r[4] = fmaxf(dd * acc[4] + b1.x, 0.0f);
        r[5] = fmaxf(dd * acc[5] + b1.y, 0.0f);
        r[6] = fmaxf(dd * acc[6] + b1.z, 0.0f);
        r[7] = fmaxf(dd * acc[7] + b1.w, 0.0f);

        if (out_half) {
            __half2 p0 = __floats2half2_rn(r[0], r[1]);
            __half2 p1 = __floats2half2_rn(r[2], r[3]);
            __half2 p2 = __floats2half2_rn(r[4], r[5]);
            __half2 p3 = __floats2half2_rn(r[6], r[7]);
            uint4 pk = make_uint4(*(unsigned*)&p0, *(unsigned*)&p1,
                                  *(unsigned*)&p2, *(unsigned*)&p3);
            *(uint4*)&((__half*)out)[(size_t)node * DIM + c] = pk;
        } else {
            float* o = (float*)out + (size_t)node * DIM + c;
            *(float4*)&o[0] = make_float4(r[0], r[1], r[2], r[3]);
            *(float4*)&o[4] = make_float4(r[4], r[5], r[6], r[7]);
        }
    }
}

// ---------------------------------------------------------------------------
// Launch
// ---------------------------------------------------------------------------
extern "C" void kernel_launch(void* const* d_in, const int* in_sizes, int n_in,
                              void* d_out, int out_size)
{
    const float* x       = (const float*)d_in[0];
    const void*  eidx    = d_in[1];
    const float* weights = (const float*)d_in[2];
    const float* biases  = (const float*)d_in[3];
    float*       out     = (float*)d_out;

    __half* h;   cudaGetSymbolAddress((void**)&h,   g_h);
    __half* act; cudaGetSymbolAddress((void**)&act, g_act);

    static int smem_set = 0;
    if (!smem_set) {
        cudaFuncSetAttribute(gemm_fp16_kernel,
                             cudaFuncAttributeMaxDynamicSharedMemorySize, GEMM_SMEM);
        smem_set = 1;
    }

    // ---- Prologue (4 kernels) ----
    init_kernel<<<SCAN_BLOCKS, 256>>>(eidx);
    hist_kernel<<<(N_EDGES / 2 + 255) / 256, 256>>>(eidx);
    scan_kernel<<<SCAN_BLOCKS, 256>>>();
    build_csr_kernel<<<(N_EDGES + 255) / 256, 256>>>(eidx, x, act);

    const int gather_blocks = (N_NODES * 32 + 255) / 256;

    for (int l = 0; l < N_LAYERS; l++) {
        const float* W = weights + (size_t)l * DIM * DIM;
        const float* b = biases + (size_t)l * DIM;
        int last = (l == N_LAYERS - 1);

        gemm_fp16_kernel<<<GEMM_GRID, 256, GEMM_SMEM>>>(act, W, h, N_NODES);
        gather_kernel<<<gather_blocks, 256>>>(h, b, last ? (void*)out : (void*)act, !last);
    }
}